// round 1
// baseline (speedup 1.0000x reference)
#include <cuda_runtime.h>
#include <cuda_bf16.h>

#define WEIGHT_POSITIVE 0.1f

static constexpr int BLOCKS  = 1024;
static constexpr int THREADS = 256;

// Scratch for block partial sums (no device allocation allowed).
__device__ float g_partials[BLOCKS];

__global__ __launch_bounds__(THREADS)
void wmse_partial_kernel(const float4* __restrict__ pred4,
                         const int4*   __restrict__ tgt4,
                         int n_vec)
{
    float sum = 0.0f;

    int stride = gridDim.x * blockDim.x;
    for (int i = blockIdx.x * blockDim.x + threadIdx.x; i < n_vec; i += stride) {
        float4 p = __ldg(&pred4[i]);
        int4   t = __ldg(&tgt4[i]);

        {
            float tf = (float)t.x;
            float d  = p.x - tf;
            bool mis = (p.x >= 0.5f) != (t.x == 1);
            sum += (mis ? (1.0f + WEIGHT_POSITIVE) : 1.0f) * d * d;
        }
        {
            float tf = (float)t.y;
            float d  = p.y - tf;
            bool mis = (p.y >= 0.5f) != (t.y == 1);
            sum += (mis ? (1.0f + WEIGHT_POSITIVE) : 1.0f) * d * d;
        }
        {
            float tf = (float)t.z;
            float d  = p.z - tf;
            bool mis = (p.z >= 0.5f) != (t.z == 1);
            sum += (mis ? (1.0f + WEIGHT_POSITIVE) : 1.0f) * d * d;
        }
        {
            float tf = (float)t.w;
            float d  = p.w - tf;
            bool mis = (p.w >= 0.5f) != (t.w == 1);
            sum += (mis ? (1.0f + WEIGHT_POSITIVE) : 1.0f) * d * d;
        }
    }

    // Warp reduce
    #pragma unroll
    for (int off = 16; off > 0; off >>= 1)
        sum += __shfl_down_sync(0xFFFFFFFFu, sum, off);

    // Block reduce via shared
    __shared__ float warp_sums[THREADS / 32];
    int lane = threadIdx.x & 31;
    int wid  = threadIdx.x >> 5;
    if (lane == 0) warp_sums[wid] = sum;
    __syncthreads();

    if (wid == 0) {
        float s = (lane < THREADS / 32) ? warp_sums[lane] : 0.0f;
        #pragma unroll
        for (int off = 16; off > 0; off >>= 1)
            s += __shfl_down_sync(0xFFFFFFFFu, s, off);
        if (lane == 0) g_partials[blockIdx.x] = s;
    }
}

__global__ __launch_bounds__(THREADS)
void wmse_final_kernel(float* __restrict__ out, float inv_n)
{
    // BLOCKS = 1024 partials, 256 threads -> 4 each
    float sum = 0.0f;
    #pragma unroll
    for (int i = threadIdx.x; i < BLOCKS; i += THREADS)
        sum += g_partials[i];

    #pragma unroll
    for (int off = 16; off > 0; off >>= 1)
        sum += __shfl_down_sync(0xFFFFFFFFu, sum, off);

    __shared__ float warp_sums[THREADS / 32];
    int lane = threadIdx.x & 31;
    int wid  = threadIdx.x >> 5;
    if (lane == 0) warp_sums[wid] = sum;
    __syncthreads();

    if (wid == 0) {
        float s = (lane < THREADS / 32) ? warp_sums[lane] : 0.0f;
        #pragma unroll
        for (int off = 16; off > 0; off >>= 1)
            s += __shfl_down_sync(0xFFFFFFFFu, s, off);
        if (lane == 0) out[0] = s * inv_n;
    }
}

extern "C" void kernel_launch(void* const* d_in, const int* in_sizes, int n_in,
                              void* d_out, int out_size)
{
    const float* pred = (const float*)d_in[0];
    const int*   tgt  = (const int*)d_in[1];
    float*       out  = (float*)d_out;
    int n = in_sizes[0];

    int n_vec = n / 4;  // N = 2^25, divisible by 4

    wmse_partial_kernel<<<BLOCKS, THREADS>>>((const float4*)pred, (const int4*)tgt, n_vec);
    wmse_final_kernel<<<1, THREADS>>>(out, 1.0f / (float)n);
}